// round 15
// baseline (speedup 1.0000x reference)
#include <cuda_runtime.h>
#include <cstdint>

// TemporalDecay: out = h + (1-m)*g*(h_fwd - h),
//   g = exp(-relu(delta*W + b)),  delta integer in [1,4],
//   h_fwd[b,t,j] = h_a[b, t-(delta-1), j]   (<= 3 rows back).
//
// R15: TMA bulk-copy staging. The register-MLP frontier of the LDG design
// saturated at 27.6us (R7/R9/R12/R14, ~6KB in flight/SM). cp.async.bulk
// moves tiles global<->shared through the TMA pipe with no register or
// L1-wavefront cost per byte; in-flight bytes/SM become smem-deep.
// Each block: one (b, 16-row) tile. Bulk-load H(19 rows incl 3-row halo),
// DL, MM -> smem (mbarrier); compute from smem (halo = smem indexing, no
// duplicate loads); bulk-store the 16KB out tile. Overlap across 4-5
// resident blocks/SM. gamma table + PDL retained.

static constexpr int Bq = 32, Tq = 2048;
static constexpr int SEGR = 16;          // rows per block
static constexpr int NSEG = Tq / SEGR;   // 128
static constexpr int THREADS = 256;
static constexpr int BLOCKS = Bq * NSEG; // 4096

// gamma[d-1][channel], 4 rows of 64 float4s (rows 1..3 read by decay).
__device__ float4 g_gamma4[4 * 64];

__global__ void gamma_precompute_kernel(const float* __restrict__ W,
                                        const float* __restrict__ bias) {
    cudaTriggerProgrammaticLaunchCompletion();
    int j = threadIdx.x;  // 0..255 channel
    float w = W[j];
    float bb = bias[j];
    float* gf = (float*)g_gamma4;
#pragma unroll
    for (int dm = 0; dm < 4; dm++) {
        float x = fmaxf(fmaf((float)(dm + 1), w, bb), 0.0f);
        gf[dm * 256 + j] = __expf(-x);
    }
}

__device__ __forceinline__ uint32_t smem_u32(const void* p) {
    uint32_t a;
    asm("{ .reg .u64 t; cvta.to.shared.u64 t, %1; cvt.u32.u64 %0, t; }"
        : "=r"(a) : "l"(p));
    return a;
}

__global__ void __launch_bounds__(THREADS, 5) decay_kernel(
    const float* __restrict__ H,      // h_a  [B*T*256]
    const float* __restrict__ DL,     // deltas [B*T*64]
    const float* __restrict__ MM,     // mask   [B*T*64]
    float* __restrict__ OUT)
{
    // smem tile: H slots 0..18 hold rows t0-3..t0+15 (slot k = row t0-3+k).
    __shared__ __align__(16) float smH[19 * 256];   // 19456 B
    __shared__ __align__(16) float smD[16 * 64];    //  4096 B
    __shared__ __align__(16) float smM[16 * 64];    //  4096 B
    __shared__ __align__(16) float smO[16 * 256];   // 16384 B
    __shared__ __align__(8)  unsigned long long mbar;

    const int tid = threadIdx.x;
    const int bb  = blockIdx.x >> 7;
    const int seg = blockIdx.x & (NSEG - 1);
    const int t0  = seg * SEGR;

    const uint32_t mbar_a = smem_u32(&mbar);

    if (tid == 0) {
        asm volatile("mbarrier.init.shared.b64 [%0], 1;" :: "r"(mbar_a) : "memory");
    }
    __syncthreads();

    if (tid == 0) {
        const int halo = (seg == 0) ? 0 : 3;   // t0==0: slots 0..2 left undefined (never selected; delta<=t+1)
        const uint32_t hbytes = (SEGR + halo) * 1024;
        const uint32_t total  = hbytes + 4096 + 4096;
        asm volatile("mbarrier.arrive.expect_tx.shared.b64 _, [%0], %1;"
                     :: "r"(mbar_a), "r"(total) : "memory");

        const char* hsrc = (const char*)H + (size_t)(bb * Tq + t0 - halo) * 1024;
        const uint32_t hdst = smem_u32(smH) + (3 - halo) * 1024;
        asm volatile("cp.async.bulk.shared::cta.global.mbarrier::complete_tx::bytes [%0], [%1], %2, [%3];"
                     :: "r"(hdst), "l"(hsrc), "r"(hbytes), "r"(mbar_a) : "memory");

        const char* dsrc = (const char*)DL + (size_t)(bb * Tq + t0) * 256;
        asm volatile("cp.async.bulk.shared::cta.global.mbarrier::complete_tx::bytes [%0], [%1], %2, [%3];"
                     :: "r"(smem_u32(smD)), "l"(dsrc), "r"(4096u), "r"(mbar_a) : "memory");

        const char* msrc = (const char*)MM + (size_t)(bb * Tq + t0) * 256;
        asm volatile("cp.async.bulk.shared::cta.global.mbarrier::complete_tx::bytes [%0], [%1], %2, [%3];"
                     :: "r"(smem_u32(smM)), "l"(msrc), "r"(4096u), "r"(mbar_a) : "memory");
    }

    // gamma table (L1-hot) — overlap with TMA; PDL sync first.
    cudaGridDependencySynchronize();
    const int col4 = tid & 63;
    const int s0   = tid >> 6;   // 0..3; this thread does rows s0, s0+4, s0+8, s0+12
    const float4 gam1 = __ldg(g_gamma4 + 1 * 64 + col4);
    const float4 gam2 = __ldg(g_gamma4 + 2 * 64 + col4);
    const float4 gam3 = __ldg(g_gamma4 + 3 * 64 + col4);

    // wait for tile arrival (parity 0)
    {
        uint32_t done;
        asm volatile(
            "{\n\t.reg .pred p;\n\t"
            "mbarrier.try_wait.parity.shared.b64 p, [%1], 0;\n\t"
            "selp.b32 %0, 1, 0, p;\n\t}"
            : "=r"(done) : "r"(mbar_a) : "memory");
        while (!done) {
            asm volatile(
                "{\n\t.reg .pred p;\n\t"
                "mbarrier.try_wait.parity.shared.b64 p, [%1], 0, 0x989680;\n\t"
                "selp.b32 %0, 1, 0, p;\n\t}"
                : "=r"(done) : "r"(mbar_a) : "memory");
        }
    }

    const float4* H4 = (const float4*)smH;
    const float4* D4 = (const float4*)smD;
    const float4* M4 = (const float4*)smM;
    float4*       O4 = (float4*)smO;

#pragma unroll
    for (int k = 0; k < 4; k++) {
        const int s = s0 + 4 * k;              // output row within tile
        const float4 ha = H4[(s + 3) * 64 + col4];
        const float4 w1 = H4[(s + 2) * 64 + col4];
        const float4 w2 = H4[(s + 1) * 64 + col4];
        const float4 w3 = H4[(s + 0) * 64 + col4];
        const float4 dl = D4[s * 16 + (col4 & 15)];
        const float4 mm = M4[s * 16 + (col4 & 15)];
        float4 o;
#define PROC(c)                                                           \
        {                                                                 \
            const float dv = dl.c;                                        \
            const float f  = (dv == 1.0f) ? ha.c                          \
                           : (dv == 2.0f) ? w1.c                          \
                           : (dv == 3.0f) ? w2.c : w3.c;                  \
            const float gv = (dv == 2.0f) ? gam1.c                        \
                           : (dv == 3.0f) ? gam2.c : gam3.c;              \
            /* dv==1 => f-ha==0, gv irrelevant */                         \
            o.c = fmaf((1.0f - mm.c) * gv, f - ha.c, ha.c);               \
        }
        PROC(x) PROC(y) PROC(z) PROC(w)
#undef PROC
        O4[s * 64 + col4] = o;
    }

    __syncthreads();
    if (tid == 0) {
        asm volatile("fence.proxy.async.shared::cta;" ::: "memory");
        char* odst = (char*)OUT + (size_t)(bb * Tq + t0) * 1024;
        asm volatile("cp.async.bulk.global.shared::cta.bulk_group [%0], [%1], %2;"
                     :: "l"(odst), "r"(smem_u32(smO)), "r"(16384u) : "memory");
        asm volatile("cp.async.bulk.commit_group;" ::: "memory");
        asm volatile("cp.async.bulk.wait_group 0;" ::: "memory");
    }
}

extern "C" void kernel_launch(void* const* d_in, const int* in_sizes, int n_in,
                              void* d_out, int out_size) {
    const float* h_a    = (const float*)d_in[0];
    const float* deltas = (const float*)d_in[1];
    const float* Mmask  = (const float*)d_in[2];
    const float* W      = (const float*)d_in[3];
    const float* b      = (const float*)d_in[4];
    float* out = (float*)d_out;

    gamma_precompute_kernel<<<1, 256>>>(W, b);

    // PDL: decay launches/overlaps while gamma runs; decay grid-dep-syncs
    // before touching the table.
    cudaLaunchAttribute attr[1];
    attr[0].id = cudaLaunchAttributeProgrammaticStreamSerialization;
    attr[0].val.programmaticStreamSerializationAllowed = 1;
    cudaLaunchConfig_t cfg = {};
    cfg.gridDim = dim3(BLOCKS);
    cfg.blockDim = dim3(THREADS);
    cfg.dynamicSmemBytes = 0;
    cfg.stream = 0;
    cfg.attrs = attr;
    cfg.numAttrs = 1;
    cudaLaunchKernelEx(&cfg, decay_kernel, h_a, deltas, Mmask, out);
}

// round 16
// speedup vs baseline: 1.0548x; 1.0548x over previous
#include <cuda_runtime.h>
#include <cstdint>

// TemporalDecay: out = h + (1-m)*g*(h_fwd - h),
//   g = exp(-relu(delta*W + b)),  delta integer in [1,4],
//   h_fwd[b,t,j] = h_a[b, t-(delta-1), j]   (<= 3 rows back).
//
// R16: persistent double-buffered TMA pipeline. R15's single-buffered TMA
// serialized load->compute->store per block (29.7us, DRAM 54.6%). Now 592
// persistent blocks (4/SM via 55KB smem) each run ~7 tiles through 2 stages:
// prefetch 2 tiles, then { wait stage; compute + STG direct from registers
// (no out-buffer, no store drain); __syncthreads; refill stage with tile+2 }.
// Up to ~220KB of tile loads in flight per SM, no register MLP bound.

static constexpr int Bq = 32, Tq = 2048;
static constexpr int SEGR = 16;            // rows per tile
static constexpr int NT = Bq * (Tq / SEGR);  // 4096 tiles
static constexpr int THREADS = 256;
static constexpr int GRID = 592;           // 4 blocks/SM * 148

static constexpr int HBYTES_FULL = 19 * 1024;  // 19456: rows t0-3..t0+15
static constexpr int DBYTES = 4096;
static constexpr int STAGE_BYTES = HBYTES_FULL + 2 * DBYTES;  // 27648
static constexpr int SMEM_TOTAL = 2 * STAGE_BYTES;            // 55296

// gamma[d-1][channel], 4 rows of 64 float4s (rows 1..3 read by decay).
__device__ float4 g_gamma4[4 * 64];

__global__ void gamma_precompute_kernel(const float* __restrict__ W,
                                        const float* __restrict__ bias) {
    cudaTriggerProgrammaticLaunchCompletion();
    int j = threadIdx.x;
    float w = W[j];
    float bb = bias[j];
    float* gf = (float*)g_gamma4;
#pragma unroll
    for (int dm = 0; dm < 4; dm++) {
        float x = fmaxf(fmaf((float)(dm + 1), w, bb), 0.0f);
        gf[dm * 256 + j] = __expf(-x);
    }
}

__device__ __forceinline__ uint32_t smem_u32(const void* p) {
    uint32_t a;
    asm("{ .reg .u64 t; cvta.to.shared.u64 t, %1; cvt.u32.u64 %0, t; }"
        : "=r"(a) : "l"(p));
    return a;
}

__device__ __forceinline__ void issue_tile(const float* H, const float* DL,
                                           const float* MM, uint32_t stage_base,
                                           uint32_t mbar_a, int tile) {
    const int bb  = tile >> 7;
    const int seg = tile & 127;
    const int t0  = seg * SEGR;
    const int halo = (seg == 0) ? 0 : 3;   // t0==0: halo slots never selected (delta<=t+1)
    const uint32_t hbytes = (SEGR + halo) * 1024;
    const uint32_t total  = hbytes + 2 * DBYTES;

    asm volatile("mbarrier.arrive.expect_tx.shared.b64 _, [%0], %1;"
                 :: "r"(mbar_a), "r"(total) : "memory");

    const char* hsrc = (const char*)H + (size_t)(bb * Tq + t0 - halo) * 1024;
    asm volatile("cp.async.bulk.shared::cta.global.mbarrier::complete_tx::bytes [%0], [%1], %2, [%3];"
                 :: "r"(stage_base + (3 - halo) * 1024), "l"(hsrc), "r"(hbytes), "r"(mbar_a) : "memory");

    const char* dsrc = (const char*)DL + (size_t)(bb * Tq + t0) * 256;
    asm volatile("cp.async.bulk.shared::cta.global.mbarrier::complete_tx::bytes [%0], [%1], %2, [%3];"
                 :: "r"(stage_base + HBYTES_FULL), "l"(dsrc), "r"((uint32_t)DBYTES), "r"(mbar_a) : "memory");

    const char* msrc = (const char*)MM + (size_t)(bb * Tq + t0) * 256;
    asm volatile("cp.async.bulk.shared::cta.global.mbarrier::complete_tx::bytes [%0], [%1], %2, [%3];"
                 :: "r"(stage_base + HBYTES_FULL + DBYTES), "l"(msrc), "r"((uint32_t)DBYTES), "r"(mbar_a) : "memory");
}

__device__ __forceinline__ void wait_parity(uint32_t mbar_a, uint32_t parity) {
    uint32_t done;
    asm volatile(
        "{\n\t.reg .pred p;\n\t"
        "mbarrier.try_wait.parity.shared.b64 p, [%1], %2;\n\t"
        "selp.b32 %0, 1, 0, p;\n\t}"
        : "=r"(done) : "r"(mbar_a), "r"(parity) : "memory");
    while (!done) {
        asm volatile(
            "{\n\t.reg .pred p;\n\t"
            "mbarrier.try_wait.parity.shared.b64 p, [%1], %2, 0x989680;\n\t"
            "selp.b32 %0, 1, 0, p;\n\t}"
            : "=r"(done) : "r"(mbar_a), "r"(parity) : "memory");
    }
}

__global__ void __launch_bounds__(THREADS) decay_kernel(
    const float* __restrict__ H,      // h_a  [B*T*256]
    const float* __restrict__ DL,     // deltas [B*T*64]
    const float* __restrict__ MM,     // mask   [B*T*64]
    float* __restrict__ OUT)
{
    extern __shared__ __align__(16) char dyn[];
    __shared__ __align__(8) unsigned long long mbar[2];

    const int tid = threadIdx.x;
    const int bid = blockIdx.x;

    const uint32_t sm_base = smem_u32(dyn);
    const uint32_t mb0 = smem_u32(&mbar[0]);
    const uint32_t mb1 = smem_u32(&mbar[1]);

    if (tid == 0) {
        asm volatile("mbarrier.init.shared.b64 [%0], 1;" :: "r"(mb0) : "memory");
        asm volatile("mbarrier.init.shared.b64 [%0], 1;" :: "r"(mb1) : "memory");
    }
    __syncthreads();

    // Prefetch tiles bid (stage 0) and bid+GRID (stage 1).
    if (tid == 0) {
        if (bid < NT)        issue_tile(H, DL, MM, sm_base,               mb0, bid);
        if (bid + GRID < NT) issue_tile(H, DL, MM, sm_base + STAGE_BYTES, mb1, bid + GRID);
    }

    // gamma table (L1-hot 4KB) — overlap with in-flight TMA; PDL sync first.
    cudaGridDependencySynchronize();
    const int col4 = tid & 63;
    const int s0   = tid >> 6;   // rows s0, s0+4, s0+8, s0+12 of each tile
    const float4 gam1 = __ldg(g_gamma4 + 1 * 64 + col4);
    const float4 gam2 = __ldg(g_gamma4 + 2 * 64 + col4);
    const float4 gam3 = __ldg(g_gamma4 + 3 * 64 + col4);

    uint32_t ph[2] = {0, 0};
    int stage = 0;
    for (int tile = bid; tile < NT; tile += GRID, stage ^= 1) {
        const uint32_t mba = stage ? mb1 : mb0;
        wait_parity(mba, ph[stage]);
        ph[stage] ^= 1;

        const char* sb = dyn + stage * STAGE_BYTES;
        const float4* H4 = (const float4*)sb;                      // slot k = row t0-3+k
        const float4* D4 = (const float4*)(sb + HBYTES_FULL);
        const float4* M4 = (const float4*)(sb + HBYTES_FULL + DBYTES);

        const int bb  = tile >> 7;
        const int t0  = (tile & 127) * SEGR;
        float4* O4 = (float4*)OUT + (size_t)(bb * Tq + t0) * 64;

#pragma unroll
        for (int k = 0; k < 4; k++) {
            const int s = s0 + 4 * k;
            const float4 ha = H4[(s + 3) * 64 + col4];
            const float4 w1 = H4[(s + 2) * 64 + col4];
            const float4 w2 = H4[(s + 1) * 64 + col4];
            const float4 w3 = H4[(s + 0) * 64 + col4];
            const float4 dl = D4[s * 16 + (col4 & 15)];
            const float4 mm = M4[s * 16 + (col4 & 15)];
            float4 o;
#define PROC(c)                                                           \
            {                                                             \
                const float dv = dl.c;                                    \
                const float f  = (dv == 1.0f) ? ha.c                      \
                               : (dv == 2.0f) ? w1.c                      \
                               : (dv == 3.0f) ? w2.c : w3.c;              \
                const float gv = (dv == 2.0f) ? gam1.c                    \
                               : (dv == 3.0f) ? gam2.c : gam3.c;          \
                /* dv==1 => f-ha==0, gv irrelevant */                     \
                o.c = fmaf((1.0f - mm.c) * gv, f - ha.c, ha.c);           \
            }
            PROC(x) PROC(y) PROC(z) PROC(w)
#undef PROC
            O4[s * 64 + col4] = o;   // direct STG.128, coalesced
        }

        __syncthreads();   // all reads of this stage done before refill
        if (tid == 0) {
            const int nt = tile + 2 * GRID;
            if (nt < NT)
                issue_tile(H, DL, MM, sm_base + stage * STAGE_BYTES, mba, nt);
        }
    }
}

extern "C" void kernel_launch(void* const* d_in, const int* in_sizes, int n_in,
                              void* d_out, int out_size) {
    const float* h_a    = (const float*)d_in[0];
    const float* deltas = (const float*)d_in[1];
    const float* Mmask  = (const float*)d_in[2];
    const float* W      = (const float*)d_in[3];
    const float* b      = (const float*)d_in[4];
    float* out = (float*)d_out;

    static bool attr_set = false;
    if (!attr_set) {
        cudaFuncSetAttribute(decay_kernel,
                             cudaFuncAttributeMaxDynamicSharedMemorySize, SMEM_TOTAL);
        attr_set = true;
    }

    gamma_precompute_kernel<<<1, 256>>>(W, b);

    // PDL: decay launches/overlaps while gamma runs; decay grid-dep-syncs
    // before touching the table.
    cudaLaunchAttribute attr[1];
    attr[0].id = cudaLaunchAttributeProgrammaticStreamSerialization;
    attr[0].val.programmaticStreamSerializationAllowed = 1;
    cudaLaunchConfig_t cfg = {};
    cfg.gridDim = dim3(GRID);
    cfg.blockDim = dim3(THREADS);
    cfg.dynamicSmemBytes = SMEM_TOTAL;
    cfg.stream = 0;
    cfg.attrs = attr;
    cfg.numAttrs = 1;
    cudaLaunchKernelEx(&cfg, decay_kernel, h_a, deltas, Mmask, out);
}

// round 17
// speedup vs baseline: 1.0656x; 1.0103x over previous
#include <cuda_runtime.h>
#include <cstdint>

// TemporalDecay: out = h + (1-m)*g*(h_fwd - h),
//   g = exp(-relu(delta*W + b)),  delta integer in [1,4],
//   h_fwd[b,t,j] = h_a[b, t-(delta-1), j]   (<= 3 rows back).
//
// R17 = R16 (persistent 2-stage TMA pipeline, 4 blocks/SM, direct STG
// epilogue) with the compute loop re-mapped: each thread handles 4
// CONSECUTIVE tile rows with a rolling 3-slot register window, so the H
// smem tile costs 7 LDS.128 per thread per tile instead of 16. L1 (59% in
// R16, the compute pacer) drops ~40%; the freed compute pace lets the TMA
// pipeline push DRAM higher.

static constexpr int Bq = 32, Tq = 2048;
static constexpr int SEGR = 16;              // rows per tile
static constexpr int NT = Bq * (Tq / SEGR);  // 4096 tiles
static constexpr int THREADS = 256;
static constexpr int GRID = 592;             // 4 blocks/SM * 148

static constexpr int HBYTES_FULL = 19 * 1024;  // rows t0-3..t0+15
static constexpr int DBYTES = 4096;
static constexpr int STAGE_BYTES = HBYTES_FULL + 2 * DBYTES;  // 27648
static constexpr int SMEM_TOTAL = 2 * STAGE_BYTES;            // 55296

// gamma[d-1][channel], 4 rows of 64 float4s (rows 1..3 read by decay).
__device__ float4 g_gamma4[4 * 64];

__global__ void gamma_precompute_kernel(const float* __restrict__ W,
                                        const float* __restrict__ bias) {
    cudaTriggerProgrammaticLaunchCompletion();
    int j = threadIdx.x;
    float w = W[j];
    float bb = bias[j];
    float* gf = (float*)g_gamma4;
#pragma unroll
    for (int dm = 0; dm < 4; dm++) {
        float x = fmaxf(fmaf((float)(dm + 1), w, bb), 0.0f);
        gf[dm * 256 + j] = __expf(-x);
    }
}

__device__ __forceinline__ uint32_t smem_u32(const void* p) {
    uint32_t a;
    asm("{ .reg .u64 t; cvta.to.shared.u64 t, %1; cvt.u32.u64 %0, t; }"
        : "=r"(a) : "l"(p));
    return a;
}

__device__ __forceinline__ void issue_tile(const float* H, const float* DL,
                                           const float* MM, uint32_t stage_base,
                                           uint32_t mbar_a, int tile) {
    const int bb  = tile >> 7;
    const int seg = tile & 127;
    const int t0  = seg * SEGR;
    const int halo = (seg == 0) ? 0 : 3;   // t0==0: halo slots never selected (delta<=t+1)
    const uint32_t hbytes = (SEGR + halo) * 1024;
    const uint32_t total  = hbytes + 2 * DBYTES;

    asm volatile("mbarrier.arrive.expect_tx.shared.b64 _, [%0], %1;"
                 :: "r"(mbar_a), "r"(total) : "memory");

    const char* hsrc = (const char*)H + (size_t)(bb * Tq + t0 - halo) * 1024;
    asm volatile("cp.async.bulk.shared::cta.global.mbarrier::complete_tx::bytes [%0], [%1], %2, [%3];"
                 :: "r"(stage_base + (3 - halo) * 1024), "l"(hsrc), "r"(hbytes), "r"(mbar_a) : "memory");

    const char* dsrc = (const char*)DL + (size_t)(bb * Tq + t0) * 256;
    asm volatile("cp.async.bulk.shared::cta.global.mbarrier::complete_tx::bytes [%0], [%1], %2, [%3];"
                 :: "r"(stage_base + HBYTES_FULL), "l"(dsrc), "r"((uint32_t)DBYTES), "r"(mbar_a) : "memory");

    const char* msrc = (const char*)MM + (size_t)(bb * Tq + t0) * 256;
    asm volatile("cp.async.bulk.shared::cta.global.mbarrier::complete_tx::bytes [%0], [%1], %2, [%3];"
                 :: "r"(stage_base + HBYTES_FULL + DBYTES), "l"(msrc), "r"((uint32_t)DBYTES), "r"(mbar_a) : "memory");
}

__device__ __forceinline__ void wait_parity(uint32_t mbar_a, uint32_t parity) {
    uint32_t done;
    asm volatile(
        "{\n\t.reg .pred p;\n\t"
        "mbarrier.try_wait.parity.shared.b64 p, [%1], %2;\n\t"
        "selp.b32 %0, 1, 0, p;\n\t}"
        : "=r"(done) : "r"(mbar_a), "r"(parity) : "memory");
    while (!done) {
        asm volatile(
            "{\n\t.reg .pred p;\n\t"
            "mbarrier.try_wait.parity.shared.b64 p, [%1], %2, 0x989680;\n\t"
            "selp.b32 %0, 1, 0, p;\n\t}"
            : "=r"(done) : "r"(mbar_a), "r"(parity) : "memory");
    }
}

__global__ void __launch_bounds__(THREADS) decay_kernel(
    const float* __restrict__ H,      // h_a  [B*T*256]
    const float* __restrict__ DL,     // deltas [B*T*64]
    const float* __restrict__ MM,     // mask   [B*T*64]
    float* __restrict__ OUT)
{
    extern __shared__ __align__(16) char dyn[];
    __shared__ __align__(8) unsigned long long mbar[2];

    const int tid = threadIdx.x;
    const int bid = blockIdx.x;

    const uint32_t sm_base = smem_u32(dyn);
    const uint32_t mb0 = smem_u32(&mbar[0]);
    const uint32_t mb1 = smem_u32(&mbar[1]);

    if (tid == 0) {
        asm volatile("mbarrier.init.shared.b64 [%0], 1;" :: "r"(mb0) : "memory");
        asm volatile("mbarrier.init.shared.b64 [%0], 1;" :: "r"(mb1) : "memory");
    }
    __syncthreads();

    // Prefetch tiles bid (stage 0) and bid+GRID (stage 1).
    if (tid == 0) {
        if (bid < NT)        issue_tile(H, DL, MM, sm_base,               mb0, bid);
        if (bid + GRID < NT) issue_tile(H, DL, MM, sm_base + STAGE_BYTES, mb1, bid + GRID);
    }

    // gamma table (L1-hot 4KB) — overlap with in-flight TMA; PDL sync first.
    cudaGridDependencySynchronize();
    const int col4 = tid & 63;
    const int s0   = tid >> 6;   // this thread: consecutive rows 4*s0 .. 4*s0+3
    const int sb0  = 4 * s0;
    const float4 gam1 = __ldg(g_gamma4 + 1 * 64 + col4);
    const float4 gam2 = __ldg(g_gamma4 + 2 * 64 + col4);
    const float4 gam3 = __ldg(g_gamma4 + 3 * 64 + col4);

    uint32_t ph[2] = {0, 0};
    int stage = 0;
    for (int tile = bid; tile < NT; tile += GRID, stage ^= 1) {
        const uint32_t mba = stage ? mb1 : mb0;
        wait_parity(mba, ph[stage]);
        ph[stage] ^= 1;

        const char* sb = dyn + stage * STAGE_BYTES;
        const float4* H4 = (const float4*)sb;                      // slot k = row t0-3+k
        const float4* D4 = (const float4*)(sb + HBYTES_FULL);
        const float4* M4 = (const float4*)(sb + HBYTES_FULL + DBYTES);

        const int bb  = tile >> 7;
        const int t0  = (tile & 127) * SEGR;
        float4* O4 = (float4*)OUT + (size_t)(bb * Tq + t0) * 64;

        // rolling window: slots sb0, sb0+1, sb0+2 = rows (4s0)-3..-1 relative
        float4 w3 = H4[(sb0 + 0) * 64 + col4];
        float4 w2 = H4[(sb0 + 1) * 64 + col4];
        float4 w1 = H4[(sb0 + 2) * 64 + col4];

#pragma unroll
        for (int k = 0; k < 4; k++) {
            const int s = sb0 + k;                       // output row in tile
            const float4 ha = H4[(s + 3) * 64 + col4];   // the one new row
            const float4 dl = D4[s * 16 + (col4 & 15)];
            const float4 mm = M4[s * 16 + (col4 & 15)];
            float4 o;
#define PROC(c)                                                           \
            {                                                             \
                const float dv = dl.c;                                    \
                const float f  = (dv == 1.0f) ? ha.c                      \
                               : (dv == 2.0f) ? w1.c                      \
                               : (dv == 3.0f) ? w2.c : w3.c;              \
                const float gv = (dv == 2.0f) ? gam1.c                    \
                               : (dv == 3.0f) ? gam2.c : gam3.c;          \
                /* dv==1 => f-ha==0, gv irrelevant */                     \
                o.c = fmaf((1.0f - mm.c) * gv, f - ha.c, ha.c);           \
            }
            PROC(x) PROC(y) PROC(z) PROC(w)
#undef PROC
            O4[s * 64 + col4] = o;   // direct STG.128, coalesced per row

            w3 = w2; w2 = w1; w1 = ha;   // register renames after unroll
        }

        __syncthreads();   // all reads of this stage done before refill
        if (tid == 0) {
            const int nt = tile + 2 * GRID;
            if (nt < NT)
                issue_tile(H, DL, MM, sm_base + stage * STAGE_BYTES, mba, nt);
        }
    }
}

extern "C" void kernel_launch(void* const* d_in, const int* in_sizes, int n_in,
                              void* d_out, int out_size) {
    const float* h_a    = (const float*)d_in[0];
    const float* deltas = (const float*)d_in[1];
    const float* Mmask  = (const float*)d_in[2];
    const float* W      = (const float*)d_in[3];
    const float* b      = (const float*)d_in[4];
    float* out = (float*)d_out;

    static bool attr_set = false;
    if (!attr_set) {
        cudaFuncSetAttribute(decay_kernel,
                             cudaFuncAttributeMaxDynamicSharedMemorySize, SMEM_TOTAL);
        attr_set = true;
    }

    gamma_precompute_kernel<<<1, 256>>>(W, b);

    // PDL: decay launches/overlaps while gamma runs; decay grid-dep-syncs
    // before touching the table.
    cudaLaunchAttribute attr[1];
    attr[0].id = cudaLaunchAttributeProgrammaticStreamSerialization;
    attr[0].val.programmaticStreamSerializationAllowed = 1;
    cudaLaunchConfig_t cfg = {};
    cfg.gridDim = dim3(GRID);
    cfg.blockDim = dim3(THREADS);
    cfg.dynamicSmemBytes = SMEM_TOTAL;
    cfg.stream = 0;
    cfg.attrs = attr;
    cfg.numAttrs = 1;
    cudaLaunchKernelEx(&cfg, decay_kernel, h_a, deltas, Mmask, out);
}